// round 4
// baseline (speedup 1.0000x reference)
#include <cuda_runtime.h>
#include <cuda_bf16.h>

// Problem constants
#define BB   4
#define NN   8192
#define EE   131072
#define HID  128
#define NF   16
#define ACT  8

// Scratch (static device globals; no allocation)
__device__ float         g_x0[BB*NN*NF];      // node features cast to float
__device__ float         g_x [BB*NN*HID];     // current node state
__device__ float         g_A [BB*NN*HID];     // dst-part node transform (+b1)
__device__ float         g_Bv[BB*NN*HID];     // src-part node transform
__device__ unsigned      g_min[BB*NN*HID];    // encoded min accumulator
__device__ unsigned char g_mask[BB*NN];       // node has >=1 in-edge

__device__ __forceinline__ float leaky(float v) { return v >= 0.f ? v : 0.01f * v; }

// monotone encoding: float -> uint preserving order (min over uints == min over floats)
__device__ __forceinline__ unsigned enc_f(float f) {
    unsigned u = __float_as_uint(f);
    return (u & 0x80000000u) ? ~u : (u | 0x80000000u);
}
__device__ __forceinline__ float dec_f(unsigned u) {
    unsigned bits = (u & 0x80000000u) ? (u ^ 0x80000000u) : ~u;
    return __uint_as_float(bits);
}

__device__ __forceinline__ int clampN(int v) {
    v = v < 0 ? 0 : v;
    return v >= NN ? NN - 1 : v;
}

// ---------------------------------------------------------------------------
// prep: cast int node features to float, zero mask
__global__ void k_prep(const int* __restrict__ nf) {
    int i = blockIdx.x * blockDim.x + threadIdx.x;
    if (i < BB*NN*NF) g_x0[i] = (float)nf[i];
    if (i < BB*NN)    g_mask[i] = 0;
}

// mask: mark nodes that receive at least one edge   (edge_index is INT32!)
__global__ void k_mask(const int* __restrict__ ei) {
    int i = blockIdx.x * blockDim.x + threadIdx.x;
    if (i >= BB*EE) return;
    int b = i / EE, e = i - b*EE;
    int dst = clampN(ei[(b*2 + 1) * EE + e]);
    g_mask[b*NN + dst] = 1;
}

__global__ void k_init_min() {
    int i = blockIdx.x * blockDim.x + threadIdx.x;
    if (i < BB*NN*HID) g_min[i] = 0xFFFFFFFFu;
}

// ---------------------------------------------------------------------------
// node transform: A[n][j] = b1[j] + sum_f x[n][f]*w1[f][j]
//                 Bv[n][j] =         sum_f x[n][f]*w1[F+f][j]
// layer==1 -> input g_x0 (F=16), else g_x (F=128)
__global__ void __launch_bounds__(HID) k_nodes(int layer,
                                               const float* __restrict__ w1,
                                               const float* __restrict__ b1) {
    int node = blockIdx.x;           // 0..BB*NN-1
    int j = threadIdx.x;             // 0..127
    const int F = (layer == 1) ? NF : HID;
    const float* x = (layer == 1) ? g_x0 : g_x;
    __shared__ float sx[HID];
    if (j < F) sx[j] = x[(size_t)node * F + j];
    __syncthreads();
    float a = __ldg(&b1[j]);
    float bb = 0.f;
    #pragma unroll 8
    for (int f = 0; f < F; f++) {
        float xv = sx[f];
        a  += xv * __ldg(&w1[f * HID + j]);
        bb += xv * __ldg(&w1[(F + f) * HID + j]);
    }
    g_A [(size_t)node * HID + j] = a;
    g_Bv[(size_t)node * HID + j] = bb;
}

// ---------------------------------------------------------------------------
// edge kernel: h = leaky(A[dst] + Bv[src] + ea*w1_edge); m = h @ w2 + b2;
//              atomicMin(encoded) into g_min[dst]
#define EPB  16   // edges per block
#define HPAD 20   // row pad: 80B, 16B-aligned for float4 reads

__global__ void __launch_bounds__(HID) k_edge(const int* __restrict__ ei,
                                              const float* __restrict__ ea,
                                              int F,
                                              const float* __restrict__ w1,
                                              const float* __restrict__ w2,
                                              const float* __restrict__ b2) {
    __shared__ __align__(16) float h[HID][HPAD];
    __shared__ int   ssrc[EPB], sdst[EPB];
    __shared__ float sea[EPB];

    const int b = blockIdx.y;
    const int base = blockIdx.x * EPB;
    const int t = threadIdx.x;

    if (t < EPB) {
        int e = base + t;
        ssrc[t] = clampN(ei[(b*2 + 0) * EE + e]);
        sdst[t] = clampN(ei[(b*2 + 1) * EE + e]);
        sea [t] = ea[(size_t)b * EE + e];
    }
    __syncthreads();

    // phase A: h[k][e]
    {
        const int k = t;
        const float w1e = __ldg(&w1[2 * F * HID + k]);   // last row of w1 (edge feature)
        const float* Ab  = g_A  + (size_t)b * NN * HID;
        const float* Bvb = g_Bv + (size_t)b * NN * HID;
        #pragma unroll
        for (int e = 0; e < EPB; e++) {
            float v = Ab[(size_t)sdst[e] * HID + k]
                    + Bvb[(size_t)ssrc[e] * HID + k]
                    + sea[e] * w1e;
            h[k][e] = leaky(v);
        }
    }
    __syncthreads();

    // phase B: m[e][j] = b2[j] + sum_k h[k][e] * w2[k][j]
    const int j = t;
    float acc[EPB];
    {
        float bias = __ldg(&b2[j]);
        #pragma unroll
        for (int e = 0; e < EPB; e++) acc[e] = bias;
    }
    #pragma unroll 4
    for (int k = 0; k < HID; k++) {
        float w = __ldg(&w2[k * HID + j]);
        const float4* hp = (const float4*)&h[k][0];
        #pragma unroll
        for (int q = 0; q < 4; q++) {
            float4 hv = hp[q];
            acc[q*4+0] += hv.x * w;
            acc[q*4+1] += hv.y * w;
            acc[q*4+2] += hv.z * w;
            acc[q*4+3] += hv.w * w;
        }
    }

    unsigned* gm = g_min + (size_t)b * NN * HID;
    #pragma unroll
    for (int e = 0; e < EPB; e++) {
        atomicMin(&gm[(size_t)sdst[e] * HID + j], enc_f(acc[e]));
    }
}

// ---------------------------------------------------------------------------
// finalize: decode min, zero isolated nodes, outer leaky -> g_x
__global__ void k_final() {
    int i = blockIdx.x * blockDim.x + threadIdx.x;
    if (i >= BB*NN*HID) return;
    int node = i / HID;
    float f = 0.f;
    if (g_mask[node]) {
        f = leaky(dec_f(g_min[i]));
    }
    g_x[i] = f;
}

// ---------------------------------------------------------------------------
// output: softplus(cat([x0, x]) @ lin_w + lin_b)
__global__ void k_out(const float* __restrict__ lw,
                      const float* __restrict__ lb,
                      float* __restrict__ out) {
    int i = blockIdx.x * blockDim.x + threadIdx.x;
    if (i >= BB*NN*ACT) return;
    int a = i & (ACT - 1);
    int node = i >> 3;
    float acc = __ldg(&lb[a]);
    const float* x0r = g_x0 + (size_t)node * NF;
    #pragma unroll
    for (int f = 0; f < NF; f++) acc += x0r[f] * __ldg(&lw[f * ACT + a]);
    const float* xr = g_x + (size_t)node * HID;
    #pragma unroll 8
    for (int f = 0; f < HID; f++) acc += xr[f] * __ldg(&lw[(NF + f) * ACT + a]);
    // stable softplus
    out[i] = (acc > 20.f) ? acc : log1pf(expf(acc));
}

// ---------------------------------------------------------------------------
extern "C" void kernel_launch(void* const* d_in, const int* in_sizes, int n_in,
                              void* d_out, int out_size) {
    const int*   nf = (const int*)d_in[0];
    const int*   ei = (const int*)d_in[1];   // int32! (JAX x64 disabled demotes int64)
    const float* ea = (const float*)d_in[2];
    const float* c1w1 = (const float*)d_in[3];
    const float* c1b1 = (const float*)d_in[4];
    const float* c1w2 = (const float*)d_in[5];
    const float* c1b2 = (const float*)d_in[6];
    const float* c2w1 = (const float*)d_in[7];
    const float* c2b1 = (const float*)d_in[8];
    const float* c2w2 = (const float*)d_in[9];
    const float* c2b2 = (const float*)d_in[10];
    const float* c3w1 = (const float*)d_in[11];
    const float* c3b1 = (const float*)d_in[12];
    const float* c3w2 = (const float*)d_in[13];
    const float* c3b2 = (const float*)d_in[14];
    const float* lw   = (const float*)d_in[15];
    const float* lb   = (const float*)d_in[16];
    float* out = (float*)d_out;

    // prep
    k_prep<<<(BB*NN*NF + 255) / 256, 256>>>(nf);
    k_mask<<<(BB*EE + 255) / 256, 256>>>(ei);

    dim3 egrid(EE / EPB, BB);

    // layer 1  (F = NF = 16)
    k_init_min<<<(BB*NN*HID + 255) / 256, 256>>>();
    k_nodes<<<BB*NN, HID>>>(1, c1w1, c1b1);
    k_edge<<<egrid, HID>>>(ei, ea, NF, c1w1, c1w2, c1b2);
    k_final<<<(BB*NN*HID + 255) / 256, 256>>>();

    // layer 2  (F = HID = 128)
    k_init_min<<<(BB*NN*HID + 255) / 256, 256>>>();
    k_nodes<<<BB*NN, HID>>>(2, c2w1, c2b1);
    k_edge<<<egrid, HID>>>(ei, ea, HID, c2w1, c2w2, c2b2);
    k_final<<<(BB*NN*HID + 255) / 256, 256>>>();

    // layer 3
    k_init_min<<<(BB*NN*HID + 255) / 256, 256>>>();
    k_nodes<<<BB*NN, HID>>>(3, c3w1, c3b1);
    k_edge<<<egrid, HID>>>(ei, ea, HID, c3w1, c3w2, c3b2);
    k_final<<<(BB*NN*HID + 255) / 256, 256>>>();

    // output head
    k_out<<<(BB*NN*ACT + 255) / 256, 256>>>(lw, lb, out);
}

// round 5
// speedup vs baseline: 1.3073x; 1.3073x over previous
#include <cuda_runtime.h>
#include <cuda_bf16.h>
#include <math_constants.h>

// Problem constants
#define BB   4
#define NN   8192
#define EE   131072
#define HID  128
#define NF   16
#define ACT  8

#define EPB  64        // edges per block in edge kernel
#define PA   132       // sA pad (words): conflict-free A frags
#define PB   136       // sB pad (words): conflict-free B frags (136%32==8)
#define SMEM_EDGE ((EPB*PA + 128*PB) * 4)

// Scratch (static device globals; no allocation)
__device__ float    g_x0 [BB*NN*NF];
__device__ float    g_x  [BB*NN*HID];
__device__ float    g_A  [BB*NN*HID];
__device__ float    g_Bv [BB*NN*HID];
__device__ unsigned g_min[BB*NN*HID];
__device__ int      g_cnt[BB*NN];      // in-degree (also isolation mask)
__device__ int      g_off[BB*NN];      // exclusive prefix of counts
__device__ int      g_cur[BB*NN];      // scatter cursors
__device__ int      g_psrc[BB*EE];     // dst-sorted src
__device__ int      g_pdst[BB*EE];     // dst-sorted dst
__device__ float    g_pea [BB*EE];     // dst-sorted edge attr

__device__ __forceinline__ float leaky(float v) { return v >= 0.f ? v : 0.01f * v; }

// monotone float->uint encoding: min over uints == min over floats
__device__ __forceinline__ unsigned enc_f(float f) {
    unsigned u = __float_as_uint(f);
    return (u & 0x80000000u) ? ~u : (u | 0x80000000u);
}
__device__ __forceinline__ float dec_f(unsigned u) {
    unsigned bits = (u & 0x80000000u) ? (u ^ 0x80000000u) : ~u;
    return __uint_as_float(bits);
}
__device__ __forceinline__ int clampN(int v) {
    v = v < 0 ? 0 : v;
    return v >= NN ? NN - 1 : v;
}
// split fp32 -> tf32 hi + tf32 lo (error ~2^-21)
__device__ __forceinline__ void split_tf(float v, unsigned &hi, unsigned &lo) {
    asm("cvt.rna.tf32.f32 %0, %1;" : "=r"(hi) : "f"(v));
    float r = v - __uint_as_float(hi);
    asm("cvt.rna.tf32.f32 %0, %1;" : "=r"(lo) : "f"(r));
}

#define MMA_TF32(c, a, b)                                                      \
    asm volatile(                                                              \
        "mma.sync.aligned.m16n8k8.row.col.f32.tf32.tf32.f32 "                  \
        "{%0,%1,%2,%3},{%4,%5,%6,%7},{%8,%9},{%0,%1,%2,%3};"                   \
        : "+f"((c)[0]), "+f"((c)[1]), "+f"((c)[2]), "+f"((c)[3])               \
        : "r"((a)[0]), "r"((a)[1]), "r"((a)[2]), "r"((a)[3]),                  \
          "r"((b)[0]), "r"((b)[1]))

// ---------------------------------------------------------------------------
__global__ void k_prep(const int* __restrict__ nf) {
    int i = blockIdx.x * blockDim.x + threadIdx.x;
    if (i < BB*NN*NF) g_x0[i] = (float)nf[i];
    if (i < BB*NN) { g_cnt[i] = 0; g_cur[i] = 0; }
}

__global__ void k_init_min() {
    int i = blockIdx.x * blockDim.x + threadIdx.x;
    if (i < BB*NN*HID) g_min[i] = 0xFFFFFFFFu;
}

// histogram of dst
__global__ void k_hist(const int* __restrict__ ei) {
    int i = blockIdx.x * blockDim.x + threadIdx.x;
    if (i >= BB*EE) return;
    int b = i / EE, e = i - b*EE;
    int dst = clampN(ei[(b*2 + 1) * EE + e]);
    atomicAdd(&g_cnt[b*NN + dst], 1);
}

// exclusive scan of 8192 bins per batch; one block of 1024 per batch
__global__ void __launch_bounds__(1024) k_scan() {
    int b = blockIdx.x;
    int t = threadIdx.x, lane = t & 31, wid = t >> 5;
    __shared__ int wsum[32];
    int base = b*NN + t*8;
    int v[8], pre[8], s = 0;
    #pragma unroll
    for (int i = 0; i < 8; i++) { v[i] = g_cnt[base+i]; pre[i] = s; s += v[i]; }
    int inc = s;
    #pragma unroll
    for (int o = 1; o < 32; o <<= 1) {
        int n = __shfl_up_sync(0xffffffffu, inc, o);
        if (lane >= o) inc += n;
    }
    if (lane == 31) wsum[wid] = inc;
    int wexcl = inc - s;
    __syncthreads();
    if (wid == 0) {
        int x = wsum[lane], xi = x;
        #pragma unroll
        for (int o = 1; o < 32; o <<= 1) {
            int n = __shfl_up_sync(0xffffffffu, xi, o);
            if (lane >= o) xi += n;
        }
        wsum[lane] = xi - x;
    }
    __syncthreads();
    int off = wsum[wid] + wexcl;
    #pragma unroll
    for (int i = 0; i < 8; i++) g_off[base+i] = off + pre[i];
}

// scatter edges into dst-sorted order (order within a dst arbitrary; min is invariant)
__global__ void k_scatter(const int* __restrict__ ei, const float* __restrict__ ea) {
    int i = blockIdx.x * blockDim.x + threadIdx.x;
    if (i >= BB*EE) return;
    int b = i / EE, e = i - b*EE;
    int src = clampN(ei[(b*2 + 0) * EE + e]);
    int dst = clampN(ei[(b*2 + 1) * EE + e]);
    float eav = ea[(size_t)b * EE + e];
    int pos = g_off[b*NN + dst] + atomicAdd(&g_cur[b*NN + dst], 1);
    g_psrc[b*EE + pos] = src;
    g_pdst[b*EE + pos] = dst;
    g_pea [b*EE + pos] = eav;
}

// ---------------------------------------------------------------------------
// node transform: A[n][j] = b1[j] + sum_f x[n][f]*w1[f][j]; Bv same with w1[F+f]
__global__ void __launch_bounds__(HID) k_nodes(int layer,
                                               const float* __restrict__ w1,
                                               const float* __restrict__ b1) {
    int node = blockIdx.x;
    int j = threadIdx.x;
    const int F = (layer == 1) ? NF : HID;
    const float* x = (layer == 1) ? g_x0 : g_x;
    __shared__ float sx[HID];
    if (j < F) sx[j] = x[(size_t)node * F + j];
    __syncthreads();
    float a = __ldg(&b1[j]);
    float bb = 0.f;
    #pragma unroll 8
    for (int f = 0; f < F; f++) {
        float xv = sx[f];
        a  += xv * __ldg(&w1[f * HID + j]);
        bb += xv * __ldg(&w1[(F + f) * HID + j]);
    }
    g_A [(size_t)node * HID + j] = a;
    g_Bv[(size_t)node * HID + j] = bb;
}

// ---------------------------------------------------------------------------
// edge kernel: gather h = leaky(A[dst]+Bv[src]+ea*w1e) into shared,
// tf32 tensor-core GEMM h@W2 (3-term split for fp32-class accuracy),
// segmented min over sorted dst, mostly-plain stores into g_min.
__global__ void __launch_bounds__(128) k_edge(int F,
                                              const float* __restrict__ w1,
                                              const float* __restrict__ w2,
                                              const float* __restrict__ b2) {
    extern __shared__ float smem[];
    float* sA = smem;              // [EPB][PA]  h tile, later m tile
    float* sB = smem + EPB * PA;   // [128][PB]  w2 tile
    __shared__ int   ssrc[EPB], sdst[EPB];
    __shared__ float sea[EPB];

    const int b    = blockIdx.y;
    const int base = blockIdx.x * EPB;
    const int t    = threadIdx.x;
    const int lane = t & 31, w = t >> 5;
    const int g    = lane >> 2, tig = lane & 3;

    if (t < EPB) {
        ssrc[t] = g_psrc[b*EE + base + t];
        sdst[t] = g_pdst[b*EE + base + t];
        sea [t] = g_pea [b*EE + base + t];
    }
    // stage w2 (fp32) into shared
    for (int i = t; i < 128*32; i += 128) {
        int k = i >> 5, jj = i & 31;
        float4 v = *(const float4*)&w2[k*128 + jj*4];
        *(float4*)&sB[k*PB + jj*4] = v;
    }
    __syncthreads();

    // gather phase: warp w handles edges [w*16, w*16+16), lane owns 4 k's
    {
        const float4 w1e = *(const float4*)&w1[2*F*HID + lane*4];
        const float* Ab  = g_A  + (size_t)b * NN * HID;
        const float* Bvb = g_Bv + (size_t)b * NN * HID;
        #pragma unroll 4
        for (int i = 0; i < 16; i++) {
            int e = w*16 + i;
            int dst = sdst[e], src = ssrc[e];
            float eav = sea[e];
            float4 a  = *(const float4*)&Ab [(size_t)dst*HID + lane*4];
            float4 bv = *(const float4*)&Bvb[(size_t)src*HID + lane*4];
            float4 h;
            h.x = leaky(a.x + bv.x + eav*w1e.x);
            h.y = leaky(a.y + bv.y + eav*w1e.y);
            h.z = leaky(a.z + bv.z + eav*w1e.z);
            h.w = leaky(a.w + bv.w + eav*w1e.w);
            *(float4*)&sA[e*PA + lane*4] = h;
        }
    }
    __syncthreads();

    // mma phase: warp w computes M=64 (all edges) x N=32 (cols [w*32, w*32+32))
    float acc[4][4][4];
    #pragma unroll
    for (int mt = 0; mt < 4; mt++)
        #pragma unroll
        for (int nt = 0; nt < 4; nt++)
            #pragma unroll
            for (int q = 0; q < 4; q++) acc[mt][nt][q] = 0.f;

    const int ncol0 = w * 32;
    for (int kt = 0; kt < 16; kt++) {
        const int c0 = kt*8 + tig;
        unsigned ahi[4][4], alo[4][4];
        #pragma unroll
        for (int mt = 0; mt < 4; mt++) {
            int r0 = mt*16 + g;
            float a0 = sA[r0*PA + c0];
            float a1 = sA[(r0+8)*PA + c0];
            float a2 = sA[r0*PA + c0 + 4];
            float a3 = sA[(r0+8)*PA + c0 + 4];
            split_tf(a0, ahi[mt][0], alo[mt][0]);
            split_tf(a1, ahi[mt][1], alo[mt][1]);
            split_tf(a2, ahi[mt][2], alo[mt][2]);
            split_tf(a3, ahi[mt][3], alo[mt][3]);
        }
        unsigned bhi[4][2], blo[4][2];
        #pragma unroll
        for (int nt = 0; nt < 4; nt++) {
            int j = ncol0 + nt*8 + g;
            float b0 = sB[(kt*8 + tig)*PB + j];
            float b1 = sB[(kt*8 + tig + 4)*PB + j];
            split_tf(b0, bhi[nt][0], blo[nt][0]);
            split_tf(b1, bhi[nt][1], blo[nt][1]);
        }
        #pragma unroll
        for (int mt = 0; mt < 4; mt++)
            #pragma unroll
            for (int nt = 0; nt < 4; nt++) {
                MMA_TF32(acc[mt][nt], ahi[mt], bhi[nt]);
                MMA_TF32(acc[mt][nt], alo[mt], bhi[nt]);
                MMA_TF32(acc[mt][nt], ahi[mt], blo[nt]);
            }
    }

    // dump m into sA (h no longer needed)
    __syncthreads();
    #pragma unroll
    for (int mt = 0; mt < 4; mt++)
        #pragma unroll
        for (int nt = 0; nt < 4; nt++) {
            int r0 = mt*16 + g;
            int j0 = ncol0 + nt*8 + tig*2;
            sA[r0*PA + j0]       = acc[mt][nt][0];
            sA[r0*PA + j0 + 1]   = acc[mt][nt][1];
            sA[(r0+8)*PA + j0]   = acc[mt][nt][2];
            sA[(r0+8)*PA + j0+1] = acc[mt][nt][3];
        }
    __syncthreads();

    // segmented min over sorted dsts; thread t owns output column j=t.
    // Interior segments (fully contained in this block) -> plain store.
    // First/last segments (may span block boundary) -> atomicMin.
    {
        const int j = t;
        const float b2j = __ldg(&b2[j]);
        unsigned* gm = g_min + (size_t)b * NN * HID;
        const int firstd = sdst[0];
        const int lastd  = sdst[EPB-1];
        float cur = CUDART_INF_F;
        int prev = firstd;
        #pragma unroll 8
        for (int e = 0; e < EPB; e++) {
            int d = sdst[e];
            float v = sA[e*PA + j];
            if (d != prev) {
                unsigned encv = enc_f(cur + b2j);
                unsigned* p = &gm[(size_t)prev * HID + j];
                if (prev == firstd || prev == lastd) atomicMin(p, encv);
                else *p = encv;
                cur = CUDART_INF_F;
                prev = d;
            }
            cur = fminf(cur, v);
        }
        atomicMin(&gm[(size_t)prev * HID + j], enc_f(cur + b2j));
    }
}

// ---------------------------------------------------------------------------
// finalize: decode min, zero isolated nodes, outer leaky -> g_x; reset g_min
__global__ void k_final() {
    int i = blockIdx.x * blockDim.x + threadIdx.x;
    if (i >= BB*NN*HID) return;
    int node = i / HID;
    unsigned m = g_min[i];
    float f = 0.f;
    if (g_cnt[node] > 0) f = leaky(dec_f(m));
    g_x[i] = f;
    g_min[i] = 0xFFFFFFFFu;   // ready for next layer / next launch
}

// ---------------------------------------------------------------------------
// output: softplus(cat([x0, x]) @ lin_w + lin_b)
__global__ void k_out(const float* __restrict__ lw,
                      const float* __restrict__ lb,
                      float* __restrict__ out) {
    int i = blockIdx.x * blockDim.x + threadIdx.x;
    if (i >= BB*NN*ACT) return;
    int a = i & (ACT - 1);
    int node = i >> 3;
    float acc = __ldg(&lb[a]);
    const float* x0r = g_x0 + (size_t)node * NF;
    #pragma unroll
    for (int f = 0; f < NF; f++) acc += x0r[f] * __ldg(&lw[f * ACT + a]);
    const float* xr = g_x + (size_t)node * HID;
    #pragma unroll 8
    for (int f = 0; f < HID; f++) acc += xr[f] * __ldg(&lw[(NF + f) * ACT + a]);
    out[i] = (acc > 20.f) ? acc : log1pf(expf(acc));
}

// ---------------------------------------------------------------------------
extern "C" void kernel_launch(void* const* d_in, const int* in_sizes, int n_in,
                              void* d_out, int out_size) {
    const int*   nf = (const int*)d_in[0];
    const int*   ei = (const int*)d_in[1];   // int32 (JAX x64 disabled)
    const float* ea = (const float*)d_in[2];
    const float* c1w1 = (const float*)d_in[3];
    const float* c1b1 = (const float*)d_in[4];
    const float* c1w2 = (const float*)d_in[5];
    const float* c1b2 = (const float*)d_in[6];
    const float* c2w1 = (const float*)d_in[7];
    const float* c2b1 = (const float*)d_in[8];
    const float* c2w2 = (const float*)d_in[9];
    const float* c2b2 = (const float*)d_in[10];
    const float* c3w1 = (const float*)d_in[11];
    const float* c3b1 = (const float*)d_in[12];
    const float* c3w2 = (const float*)d_in[13];
    const float* c3b2 = (const float*)d_in[14];
    const float* lw   = (const float*)d_in[15];
    const float* lb   = (const float*)d_in[16];
    float* out = (float*)d_out;

    cudaFuncSetAttribute(k_edge, cudaFuncAttributeMaxDynamicSharedMemorySize, SMEM_EDGE);

    // prep + sort (graph topology reused by all three layers)
    k_prep<<<(BB*NN*NF + 255) / 256, 256>>>(nf);
    k_hist<<<(BB*EE + 255) / 256, 256>>>(ei);
    k_scan<<<BB, 1024>>>();
    k_scatter<<<(BB*EE + 255) / 256, 256>>>(ei, ea);
    k_init_min<<<(BB*NN*HID + 255) / 256, 256>>>();

    dim3 egrid(EE / EPB, BB);

    // layer 1 (F = NF)
    k_nodes<<<BB*NN, HID>>>(1, c1w1, c1b1);
    k_edge<<<egrid, 128, SMEM_EDGE>>>(NF, c1w1, c1w2, c1b2);
    k_final<<<(BB*NN*HID + 255) / 256, 256>>>();

    // layer 2 (F = HID)
    k_nodes<<<BB*NN, HID>>>(2, c2w1, c2b1);
    k_edge<<<egrid, 128, SMEM_EDGE>>>(HID, c2w1, c2w2, c2b2);
    k_final<<<(BB*NN*HID + 255) / 256, 256>>>();

    // layer 3
    k_nodes<<<BB*NN, HID>>>(3, c3w1, c3b1);
    k_edge<<<egrid, 128, SMEM_EDGE>>>(HID, c3w1, c3w2, c3b2);
    k_final<<<(BB*NN*HID + 255) / 256, 256>>>();

    // output head
    k_out<<<(BB*NN*ACT + 255) / 256, 256>>>(lw, lb, out);
}